// round 2
// baseline (speedup 1.0000x reference)
#include <cuda_runtime.h>
#include <math.h>

#define N_ 199
#define F_ 64
#define H_ 4
#define U_ 64
#define B_ 512
#define OUTC_ (H_*U_ + N_)   // 455
#define KT_PITCH 68          // padded K^T row pitch (floats), 16B-aligned rows

// Scratch (static __device__ allowed; no runtime alloc)
__device__ int   g_deg[N_];
__device__ int   g_nbrs[N_ * N_];
__device__ float g_awv[H_ * N_ * N_];

// ---------------------------------------------------------------------------
// Prep: build per-row neighbor lists (A is symmetric, diag=1) and gather
// AW^T values: g_awv[h][m][k] = A[n][m] * params[h][n][m], n = k-th neighbor.
// ---------------------------------------------------------------------------
__global__ void prep_kernel(const float* __restrict__ A,
                            const float* __restrict__ params)
{
    const int m = blockIdx.x;
    __shared__ int s_nb[N_];
    __shared__ int s_d;
    const int tid = threadIdx.x;
    if (tid == 0) {
        int d = 0;
        const float* arow = A + (size_t)m * N_;
        for (int n = 0; n < N_; n++)
            if (arow[n] != 0.0f) s_nb[d++] = n;
        s_d = d;
        g_deg[m] = d;
    }
    __syncthreads();
    const int d = s_d;
    for (int i = tid; i < d; i += blockDim.x) g_nbrs[m * N_ + i] = s_nb[i];
    for (int i = tid; i < d * H_; i += blockDim.x) {
        int h = i / d, k = i - h * d;
        int n = s_nb[k];
        g_awv[((size_t)h * N_ + m) * N_ + k] =
            A[(size_t)n * N_ + m] * params[((size_t)h * N_ + n) * N_ + m];
    }
}

// ---------------------------------------------------------------------------
// Main: one CTA per (h, b). 16 warps; warp w handles rows m = w, w+16, ...
// Per row (degree d ~ 31):
//   feat[f]  = sum_k aw[k] * X[nbr[k]][f]                (sparse)
//   dense[j] = b1[j] + sum_f feat[f]*K[f][j], j in nbrs  (sparse cols, K^T f4)
//   mask     = softmax over neighbor entries (others exactly 0)
//   node[f]  = sum_k mask[k] * X[nbr[k]][f]              (sparse)
//   out[u]   = b2[u] + sum_f node[f]*fc[f][u]
// Output row (b,m): cols [0,256) = heads, cols [256,455) = mask of head H-1.
// ---------------------------------------------------------------------------
__global__ __launch_bounds__(512, 1)
void gc_main(const float* __restrict__ X, const float* __restrict__ kernels,
             const float* __restrict__ fc, const float* __restrict__ bias1,
             const float* __restrict__ bias2, float* __restrict__ out)
{
    extern __shared__ float smf[];
    const int h = blockIdx.x;
    const int b = blockIdx.y;

    float* Xs  = smf;                      // 199*64   = 12736
    float* KT  = Xs + N_ * F_;             // 199*68   = 13532 (K transposed, padded)
    float* FCs = KT + N_ * KT_PITCH;       // 64*64    = 4096
    float* b1s = FCs + F_ * U_;            // 200
    float* b2s = b1s + 200;                // 64
    float* wbase = b2s + 64;               // 16 warps * 464 floats

    const int tid  = threadIdx.x;
    const int w    = tid >> 5;
    const int lane = tid & 31;

    float*  fn   = wbase + w * 464;        // 64: feat, later node (f-linear)
    float2* nav  = (float2*)(fn + 64);     // 200 x {n(bitcast int), av/mask}
    float*  navf = (float*)nav;

    // ---- cooperative loads ----
    const float* Xb = X + (size_t)b * (N_ * F_);
    for (int i = tid; i < N_ * F_; i += 512) Xs[i] = Xb[i];
    const float* Kh = kernels + (size_t)h * (F_ * N_);
    for (int i = tid; i < F_ * N_; i += 512) {
        int f = i / N_, j = i - f * N_;
        KT[j * KT_PITCH + f] = Kh[i];
    }
    const float* Fh = fc + (size_t)h * (F_ * U_);
    for (int i = tid; i < F_ * U_; i += 512) FCs[i] = Fh[i];
    for (int i = tid; i < N_; i += 512) b1s[i] = bias1[h * N_ + i];
    if (tid < U_) b2s[tid] = bias2[h * U_ + tid];
    __syncthreads();

    const float2* Xs2 = (const float2*)Xs;

    for (int m = w; m < N_; m += 16) {
        const int d = g_deg[m];
        const int* nbg = g_nbrs + m * N_;
        const float* avg_ = g_awv + ((size_t)h * N_ + m) * N_;
        for (int k = lane; k < d; k += 32)
            nav[k] = make_float2(__int_as_float(nbg[k]), avg_[k]);
        __syncwarp();

        // ---- feat: lanes cover f = 2*lane, 2*lane+1 ----
        float f0 = 0.f, f1 = 0.f;
        #pragma unroll 4
        for (int k = 0; k < d; k++) {
            float2 v = nav[k];
            int n = __float_as_int(v.x);
            float2 xv = Xs2[n * 32 + lane];
            f0 += v.y * xv.x;
            f1 += v.y * xv.y;
        }
        ((float2*)fn)[lane] = make_float2(f0, f1);
        __syncwarp();

        // ---- dense at neighbor columns only (float4 over f) ----
        float lmax = -3.0e38f;
        for (int k = lane; k < d; k += 32) {
            int j = __float_as_int(nav[k].x);
            const float4* kp = (const float4*)(KT + j * KT_PITCH);
            const float4* fp = (const float4*)fn;
            float acc = b1s[j];
            #pragma unroll
            for (int g = 0; g < 16; g++) {
                float4 kv = kp[g], fv = fp[g];
                acc += fv.x * kv.x; acc += fv.y * kv.y;
                acc += fv.z * kv.z; acc += fv.w * kv.w;
            }
            navf[2 * k + 1] = acc;              // stash dense value
            lmax = fmaxf(lmax, acc);
        }
        #pragma unroll
        for (int off = 16; off; off >>= 1)
            lmax = fmaxf(lmax, __shfl_xor_sync(0xffffffffu, lmax, off));
        __syncwarp();

        float lsum = 0.f;
        for (int k = lane; k < d; k += 32) {
            float e = __expf(navf[2 * k + 1] - lmax);
            navf[2 * k + 1] = e;
            lsum += e;
        }
        #pragma unroll
        for (int off = 16; off; off >>= 1)
            lsum += __shfl_xor_sync(0xffffffffu, lsum, off);
        const float inv = 1.f / lsum;
        __syncwarp();
        for (int k = lane; k < d; k += 32) navf[2 * k + 1] *= inv;
        __syncwarp();

        // ---- node (same sparse pattern, mask weights now in nav[k].y) ----
        float n0 = 0.f, n1 = 0.f;
        #pragma unroll 4
        for (int k = 0; k < d; k++) {
            float2 v = nav[k];
            int j = __float_as_int(v.x);
            float2 xv = Xs2[j * 32 + lane];
            n0 += v.y * xv.x;
            n1 += v.y * xv.y;
        }
        __syncwarp();
        ((float2*)fn)[lane] = make_float2(n0, n1);
        __syncwarp();

        // ---- out: u = lane, lane+32 ----
        float o0 = b2s[lane], o1 = b2s[lane + 32];
        #pragma unroll 8
        for (int f = 0; f < F_; f++) {
            float nf = fn[f];
            o0 += nf * FCs[f * U_ + lane];
            o1 += nf * FCs[f * U_ + lane + 32];
        }
        float* orow = out + ((size_t)b * N_ + m) * OUTC_;
        orow[h * U_ + lane]      = o0;
        orow[h * U_ + lane + 32] = o1;

        // ---- last head also emits its (sparse) mask row, zeros elsewhere ----
        if (h == H_ - 1) {
            float* mrow = orow + H_ * U_;
            for (int j = lane; j < N_; j += 32) mrow[j] = 0.f;
            __syncwarp();
            for (int k = lane; k < d; k += 32)
                mrow[__float_as_int(nav[k].x)] = navf[2 * k + 1];
        }
    }
}

// ---------------------------------------------------------------------------
extern "C" void kernel_launch(void* const* d_in, const int* in_sizes, int n_in,
                              void* d_out, int out_size)
{
    const float* X  = (const float*)d_in[0];
    const float* A  = (const float*)d_in[1];
    const float* K  = (const float*)d_in[2];
    const float* P  = (const float*)d_in[3];
    const float* FC = (const float*)d_in[4];
    const float* B1 = (const float*)d_in[5];
    const float* B2 = (const float*)d_in[6];
    float* out = (float*)d_out;

    const int smem_bytes = (12736 + 13532 + 4096 + 200 + 64 + 16 * 464) * 4; // 152208
    cudaFuncSetAttribute((const void*)gc_main,
                         cudaFuncAttributeMaxDynamicSharedMemorySize, smem_bytes);

    prep_kernel<<<N_, 128>>>(A, P);
    dim3 grid(H_, B_);
    gc_main<<<grid, 512, smem_bytes>>>(X, K, FC, B1, B2, out);
}

// round 3
// speedup vs baseline: 1.1386x; 1.1386x over previous
#include <cuda_runtime.h>
#include <math.h>

#define N_ 199
#define F_ 64
#define H_ 4
#define U_ 64
#define B_ 512
#define OUTC_ (H_*U_ + N_)   // 455
#define KT_PITCH 68          // padded K^T row pitch (floats); 17 quads (odd) for LDS.128

// Static scratch (no runtime allocation allowed)
__device__ int   g_deg[N_];
__device__ int   g_nbrs[N_ * N_];
__device__ float g_awv[H_ * N_ * N_];

// ---------------------------------------------------------------------------
// Prep: per-row neighbor lists + gathered AW^T values:
// g_awv[h][m][k] = A[n][m]*params[h][n][m], n = k-th neighbor of m.
// ---------------------------------------------------------------------------
__global__ void prep_kernel(const float* __restrict__ A,
                            const float* __restrict__ params)
{
    const int m = blockIdx.x;
    __shared__ int s_nb[N_];
    __shared__ int s_d;
    const int tid = threadIdx.x;
    if (tid == 0) {
        int d = 0;
        const float* arow = A + (size_t)m * N_;
        for (int n = 0; n < N_; n++)
            if (arow[n] != 0.0f) s_nb[d++] = n;
        s_d = d;
        g_deg[m] = d;
    }
    __syncthreads();
    const int d = s_d;
    for (int i = tid; i < d; i += blockDim.x) g_nbrs[m * N_ + i] = s_nb[i];
    for (int i = tid; i < d * H_; i += blockDim.x) {
        int h = i / d, k = i - h * d;
        int n = s_nb[k];
        g_awv[((size_t)h * N_ + m) * N_ + k] =
            A[(size_t)n * N_ + m] * params[((size_t)h * N_ + n) * N_ + m];
    }
}

// ---------------------------------------------------------------------------
// Main: one CTA per (h, b). Phase 1: Y = X@fc + bias2 (dense, 8-row blocked).
// Phase 2 (per row m, warp-owned):
//   feat[f]  = sum_k aw[k]*X[n_k][f]          (sparse gather)
//   dense[j] = b1[j] + feat . K[:,j], j in nbrs (KT float4 gather)
//   mask     = softmax over neighbors (exact zeros elsewhere)
//   out[u]   = sum_k mask[k]*Y[n_k][u]        (sparse gather; bias2 via sum(mask)=1)
// ---------------------------------------------------------------------------
__global__ __launch_bounds__(512, 1)
void gc_main(const float* __restrict__ X, const float* __restrict__ kernels,
             const float* __restrict__ fc, const float* __restrict__ bias1,
             const float* __restrict__ bias2, float* __restrict__ out)
{
    extern __shared__ float smf[];
    const int h = blockIdx.x;
    const int b = blockIdx.y;

    float* Xs  = smf;                      // 199*64  = 12736
    float* KT  = Xs + N_ * F_;             // 199*68  = 13532
    float* Ys  = KT + N_ * KT_PITCH;       // 199*64  = 12736
    float* FCs = Ys + N_ * U_;             // 64*64   = 4096
    float* b1s = FCs + F_ * U_;            // 200
    float* b2s = b1s + 200;                // 64
    float* wbase = b2s + 64;               // 16 warps * (64 + 400) floats

    const int tid  = threadIdx.x;
    const int w    = tid >> 5;
    const int lane = tid & 31;

    float*  fn   = wbase + w * 464;        // 64 floats: feat (float4-aligned)
    float2* nav  = (float2*)(fn + 64);     // 200 x {n (bitcast int), aw/mask}
    float*  navf = (float*)nav;

    // ---- cooperative loads ----
    const float* Xb = X + (size_t)b * (N_ * F_);
    for (int i = tid; i < N_ * F_; i += 512) Xs[i] = Xb[i];
    const float* Kh = kernels + (size_t)h * (F_ * N_);
    for (int i = tid; i < F_ * N_; i += 512) {
        int f = i / N_, j = i - f * N_;
        KT[j * KT_PITCH + f] = Kh[i];
    }
    const float* Fh = fc + (size_t)h * (F_ * U_);
    for (int i = tid; i < F_ * U_; i += 512) FCs[i] = Fh[i];
    for (int i = tid; i < N_; i += 512) b1s[i] = bias1[h * N_ + i];
    if (tid < U_) b2s[tid] = bias2[h * U_ + tid];
    __syncthreads();

    // ================= Phase 1: Ys = Xs @ FCs + b2 =================
    // Warp handles 8 consecutive rows; lanes cover u=lane, u+32.
    // f processed in float4 groups to minimize broadcast phases.
    {
        const float bb0 = b2s[lane], bb1 = b2s[lane + 32];
        for (int base = 0; base < N_; base += 128) {
            const int m0 = base + w * 8;
            if (m0 >= N_) continue;
            const int rows = (N_ - m0 >= 8) ? 8 : (N_ - m0);
            float a0[8], a1[8];
            #pragma unroll
            for (int r = 0; r < 8; r++) { a0[r] = bb0; a1[r] = bb1; }
            if (rows == 8) {
                #pragma unroll 4
                for (int f4 = 0; f4 < F_ / 4; f4++) {
                    float4 xv[8];
                    #pragma unroll
                    for (int r = 0; r < 8; r++)
                        xv[r] = ((const float4*)(Xs + (m0 + r) * F_))[f4];
                    #pragma unroll
                    for (int ff = 0; ff < 4; ff++) {
                        const int f = 4 * f4 + ff;
                        const float c0 = FCs[f * U_ + lane];
                        const float c1 = FCs[f * U_ + lane + 32];
                        #pragma unroll
                        for (int r = 0; r < 8; r++) {
                            const float x = (ff == 0) ? xv[r].x : (ff == 1) ? xv[r].y
                                          : (ff == 2) ? xv[r].z : xv[r].w;
                            a0[r] += x * c0;
                            a1[r] += x * c1;
                        }
                    }
                }
                #pragma unroll
                for (int r = 0; r < 8; r++) {
                    Ys[(m0 + r) * U_ + lane]      = a0[r];
                    Ys[(m0 + r) * U_ + lane + 32] = a1[r];
                }
            } else {
                for (int f = 0; f < F_; f++) {
                    const float c0 = FCs[f * U_ + lane];
                    const float c1 = FCs[f * U_ + lane + 32];
                    for (int r = 0; r < rows; r++) {
                        const float x = Xs[(m0 + r) * F_ + f];
                        a0[r] += x * c0;
                        a1[r] += x * c1;
                    }
                }
                for (int r = 0; r < rows; r++) {
                    Ys[(m0 + r) * U_ + lane]      = a0[r];
                    Ys[(m0 + r) * U_ + lane + 32] = a1[r];
                }
            }
        }
    }
    __syncthreads();

    // ================= Phase 2: per-row sparse pipeline =================
    const float2* Xs2 = (const float2*)Xs;

    for (int m = w; m < N_; m += 16) {
        const int d = g_deg[m];
        const int* __restrict__ nbg = g_nbrs + m * N_;
        const float* __restrict__ avg_ = g_awv + ((size_t)h * N_ + m) * N_;
        for (int k = lane; k < d; k += 32)
            nav[k] = make_float2(__int_as_float(nbg[k]), avg_[k]);
        __syncwarp();

        // ---- feat: lanes cover f = 2*lane, 2*lane+1 ----
        float f0 = 0.f, f1 = 0.f;
        #pragma unroll 4
        for (int k = 0; k < d; k++) {
            float2 v = nav[k];
            int n = __float_as_int(v.x);
            float2 xv = Xs2[n * 32 + lane];
            f0 += v.y * xv.x;
            f1 += v.y * xv.y;
        }
        ((float2*)fn)[lane] = make_float2(f0, f1);
        __syncwarp();

        // ---- dense at neighbor columns (float4 over f; pitch 17 quads) ----
        float lmax = -3.0e38f;
        for (int k = lane; k < d; k += 32) {
            int j = __float_as_int(nav[k].x);
            const float4* kp = (const float4*)(KT + j * KT_PITCH);
            const float4* fp = (const float4*)fn;
            float acc = b1s[j];
            #pragma unroll
            for (int g = 0; g < 16; g++) {
                float4 kv = kp[g], fv = fp[g];
                acc += fv.x * kv.x; acc += fv.y * kv.y;
                acc += fv.z * kv.z; acc += fv.w * kv.w;
            }
            navf[2 * k + 1] = acc;
            lmax = fmaxf(lmax, acc);
        }
        #pragma unroll
        for (int off = 16; off; off >>= 1)
            lmax = fmaxf(lmax, __shfl_xor_sync(0xffffffffu, lmax, off));
        __syncwarp();

        float lsum = 0.f;
        for (int k = lane; k < d; k += 32) {
            float e = __expf(navf[2 * k + 1] - lmax);
            navf[2 * k + 1] = e;
            lsum += e;
        }
        #pragma unroll
        for (int off = 16; off; off >>= 1)
            lsum += __shfl_xor_sync(0xffffffffu, lsum, off);
        const float inv = 1.f / lsum;
        __syncwarp();
        for (int k = lane; k < d; k += 32) navf[2 * k + 1] *= inv;
        __syncwarp();

        // ---- out-gather from Ys: out[u] = sum_k mask[k]*Y[n_k][u] ----
        float o0 = 0.f, o1 = 0.f;
        #pragma unroll 4
        for (int k = 0; k < d; k++) {
            float2 v = nav[k];
            int n = __float_as_int(v.x);
            o0 += v.y * Ys[n * U_ + lane];
            o1 += v.y * Ys[n * U_ + lane + 32];
        }
        float* orow = out + ((size_t)b * N_ + m) * OUTC_;
        orow[h * U_ + lane]      = o0;
        orow[h * U_ + lane + 32] = o1;

        // ---- last head also emits its sparse mask row ----
        if (h == H_ - 1) {
            float* mrow = orow + H_ * U_;
            for (int j = lane; j < N_; j += 32) mrow[j] = 0.f;
            __syncwarp();
            for (int k = lane; k < d; k += 32)
                mrow[__float_as_int(nav[k].x)] = navf[2 * k + 1];
        }
    }
}

// ---------------------------------------------------------------------------
extern "C" void kernel_launch(void* const* d_in, const int* in_sizes, int n_in,
                              void* d_out, int out_size)
{
    const float* X  = (const float*)d_in[0];
    const float* A  = (const float*)d_in[1];
    const float* K  = (const float*)d_in[2];
    const float* P  = (const float*)d_in[3];
    const float* FC = (const float*)d_in[4];
    const float* B1 = (const float*)d_in[5];
    const float* B2 = (const float*)d_in[6];
    float* out = (float*)d_out;

    const int smem_bytes =
        (N_*F_ + N_*KT_PITCH + N_*U_ + F_*U_ + 200 + 64 + 16 * 464) * 4; // 203152
    cudaFuncSetAttribute((const void*)gc_main,
                         cudaFuncAttributeMaxDynamicSharedMemorySize, smem_bytes);

    prep_kernel<<<N_, 128>>>(A, P);
    dim3 grid(H_, B_);
    gc_main<<<grid, 512, smem_bytes>>>(X, K, FC, B1, B2, out);
}

// round 5
// speedup vs baseline: 1.1427x; 1.0036x over previous
#include <cuda_runtime.h>
#include <math.h>

#define N_ 199
#define F_ 64
#define H_ 4
#define U_ 64
#define B_ 512
#define OUTC_ (H_*U_ + N_)   // 455 (odd! out rows are only 4B-aligned)
#define KT_PITCH 68          // padded K^T row pitch (floats)
#define MAXCH 7              // chunk regs cover d <= 224 (> N, always safe)

// Static scratch
__device__ int   g_deg[N_];
__device__ int   g_nbrs[N_ * N_];   // stores n*32 (pre-scaled float2-row index)
__device__ float g_awv[H_ * N_ * N_];

// ---------------------------------------------------------------------------
// Prep: neighbor lists (pre-scaled by 32) + gathered AW^T values.
// ---------------------------------------------------------------------------
__global__ void prep_kernel(const float* __restrict__ A,
                            const float* __restrict__ params)
{
    const int m = blockIdx.x;
    __shared__ int s_nb[N_];
    __shared__ int s_d;
    const int tid = threadIdx.x;
    if (tid == 0) {
        int d = 0;
        const float* arow = A + (size_t)m * N_;
        for (int n = 0; n < N_; n++)
            if (arow[n] != 0.0f) s_nb[d++] = n;
        s_d = d;
        g_deg[m] = d;
    }
    __syncthreads();
    const int d = s_d;
    for (int i = tid; i < d; i += blockDim.x) g_nbrs[m * N_ + i] = s_nb[i] * 32;
    for (int i = tid; i < d * H_; i += blockDim.x) {
        int h = i / d, k = i - h * d;
        int n = s_nb[k];
        g_awv[((size_t)h * N_ + m) * N_ + k] =
            A[(size_t)n * N_ + m] * params[((size_t)h * N_ + n) * N_ + m];
    }
}

// ---------------------------------------------------------------------------
// Main: one CTA per (h, b).
// Phase 1: Ys = Xs @ fc + bias2 (interleaved float2 layout, lane owns u=2l,2l+1)
// Phase 2 per row m (one warp):
//   feat = sparse gather over Xs; dense at neighbor cols (KT f4 gather);
//   register softmax (chunked); out = mask-gather over Ys (float2 smem reads,
//   scalar global stores — OUTC_ is odd so rows are only 4B-aligned).
// ---------------------------------------------------------------------------
__global__ __launch_bounds__(512, 1)
void gc_main(const float* __restrict__ X, const float* __restrict__ kernels,
             const float* __restrict__ fc, const float* __restrict__ bias1,
             const float* __restrict__ bias2, float* __restrict__ out)
{
    extern __shared__ float smf[];
    const int h = blockIdx.x;
    const int b = blockIdx.y;

    float*  Xs   = smf;                       // 199*64  floats
    float*  KT   = Xs + N_ * F_;              // 199*68
    float2* Ys2  = (float2*)(KT + N_ * KT_PITCH);   // 199*32 float2
    float2* FC2  = Ys2 + N_ * 32;             // 64*32 float2
    float*  b1s  = (float*)(FC2 + F_ * 32);   // 200
    float2* b2s2 = (float2*)(b1s + 200);      // 32 float2
    float*  wbase = (float*)(b2s2 + 32);      // 16 warps * 464 floats

    const int tid  = threadIdx.x;
    const int w    = tid >> 5;
    const int lane = tid & 31;

    float2* fn2  = (float2*)(wbase + w * 464);  // 32 float2: feat
    float4* fn4  = (float4*)fn2;
    float2* nav  = (float2*)(fn2 + 32);         // 200 x {idx*32 (bitcast), aw/mask}
    float*  navf = (float*)nav;

    // ---- cooperative loads ----
    const float* Xb = X + (size_t)b * (N_ * F_);
    for (int i = tid; i < N_ * F_; i += 512) Xs[i] = Xb[i];
    const float* Kh = kernels + (size_t)h * (F_ * N_);
    for (int i = tid; i < F_ * N_; i += 512) {
        int f = i / N_, j = i - f * N_;
        KT[j * KT_PITCH + f] = Kh[i];
    }
    const float2* Fh2 = (const float2*)(fc + (size_t)h * (F_ * U_));
    for (int i = tid; i < F_ * 32; i += 512) FC2[i] = Fh2[i];
    for (int i = tid; i < N_; i += 512) b1s[i] = bias1[h * N_ + i];
    if (tid < 32) b2s2[tid] = ((const float2*)(bias2 + h * U_))[tid];
    __syncthreads();

    // ================= Phase 1: Ys2 = Xs @ FC2 + b2 =================
    {
        const float2 bb = b2s2[lane];
        for (int base = 0; base < N_; base += 128) {
            const int m0 = base + w * 8;
            if (m0 >= N_) continue;
            const int rows = (N_ - m0 >= 8) ? 8 : (N_ - m0);
            float2 acc[8];
            #pragma unroll
            for (int r = 0; r < 8; r++) acc[r] = bb;
            if (rows == 8) {
                #pragma unroll 4
                for (int f4 = 0; f4 < F_ / 4; f4++) {
                    float4 xv[8];
                    #pragma unroll
                    for (int r = 0; r < 8; r++)
                        xv[r] = ((const float4*)(Xs + (m0 + r) * F_))[f4];
                    #pragma unroll
                    for (int ff = 0; ff < 4; ff++) {
                        const float2 c = FC2[(4 * f4 + ff) * 32 + lane];
                        #pragma unroll
                        for (int r = 0; r < 8; r++) {
                            const float x = (ff == 0) ? xv[r].x : (ff == 1) ? xv[r].y
                                          : (ff == 2) ? xv[r].z : xv[r].w;
                            acc[r].x += x * c.x;
                            acc[r].y += x * c.y;
                        }
                    }
                }
                #pragma unroll
                for (int r = 0; r < 8; r++) Ys2[(m0 + r) * 32 + lane] = acc[r];
            } else {
                for (int f = 0; f < F_; f++) {
                    const float2 c = FC2[f * 32 + lane];
                    for (int r = 0; r < rows; r++) {
                        const float x = Xs[(m0 + r) * F_ + f];
                        acc[r].x += x * c.x;
                        acc[r].y += x * c.y;
                    }
                }
                for (int r = 0; r < rows; r++) Ys2[(m0 + r) * 32 + lane] = acc[r];
            }
        }
    }
    __syncthreads();

    // ================= Phase 2: per-row sparse pipeline =================
    const float2* Xs2 = (const float2*)Xs;

    for (int m = w; m < N_; m += 16) {
        const int d = g_deg[m];
        const int* __restrict__ nbg = g_nbrs + m * N_;
        const float* __restrict__ avg_ = g_awv + ((size_t)h * N_ + m) * N_;
        for (int k = lane; k < d; k += 32)
            nav[k] = make_float2(__int_as_float(nbg[k]), avg_[k]);
        __syncwarp();

        // ---- feat: lanes cover f = 2*lane, 2*lane+1 ----
        float2 fa = make_float2(0.f, 0.f);
        #pragma unroll 4
        for (int k = 0; k < d; k++) {
            float2 v = nav[k];
            float2 xv = Xs2[__float_as_int(v.x) + lane];
            fa.x += v.y * xv.x;
            fa.y += v.y * xv.y;
        }
        fn2[lane] = fa;
        __syncwarp();

        // ---- dense chunks in registers (lane owns k = c*32 + lane) ----
        const int nch = (d + 31) >> 5;
        float e[MAXCH];
        float lmax = -3.0e38f;
        #pragma unroll
        for (int c = 0; c < MAXCH; c++) {
            if (c >= nch) break;
            const int k = c * 32 + lane;
            float acc = -3.0e38f;
            if (k < d) {
                const int j = __float_as_int(nav[k].x) >> 5;
                const float4* kp = (const float4*)(KT + j * KT_PITCH);
                acc = b1s[j];
                #pragma unroll
                for (int g = 0; g < 16; g++) {
                    float4 kv = kp[g], fv = fn4[g];
                    acc += fv.x * kv.x; acc += fv.y * kv.y;
                    acc += fv.z * kv.z; acc += fv.w * kv.w;
                }
            }
            e[c] = acc;
            lmax = fmaxf(lmax, acc);
        }
        #pragma unroll
        for (int off = 16; off; off >>= 1)
            lmax = fmaxf(lmax, __shfl_xor_sync(0xffffffffu, lmax, off));

        float lsum = 0.f;
        #pragma unroll
        for (int c = 0; c < MAXCH; c++) {
            if (c >= nch) break;
            const int k = c * 32 + lane;
            float ex = (k < d) ? __expf(e[c] - lmax) : 0.f;
            e[c] = ex;
            lsum += ex;
        }
        #pragma unroll
        for (int off = 16; off; off >>= 1)
            lsum += __shfl_xor_sync(0xffffffffu, lsum, off);
        const float inv = 1.f / lsum;

        #pragma unroll
        for (int c = 0; c < MAXCH; c++) {
            if (c >= nch) break;
            const int k = c * 32 + lane;
            if (k < d) navf[2 * k + 1] = e[c] * inv;   // mask into nav.y
        }
        __syncwarp();

        // ---- out-gather from Ys2 (float2 smem reads) ----
        float2 oa = make_float2(0.f, 0.f);
        #pragma unroll 4
        for (int k = 0; k < d; k++) {
            float2 v = nav[k];
            float2 yv = Ys2[__float_as_int(v.x) + lane];
            oa.x += v.y * yv.x;
            oa.y += v.y * yv.y;
        }
        // scalar stores: OUTC_=455 (odd) -> float2 STG would be misaligned
        float* orow = out + ((size_t)b * N_ + m) * OUTC_;
        orow[h * U_ + 2 * lane]     = oa.x;
        orow[h * U_ + 2 * lane + 1] = oa.y;

        // ---- last head also emits its sparse mask row ----
        if (h == H_ - 1) {
            float* mrow = orow + H_ * U_;
            for (int j = lane; j < N_; j += 32) mrow[j] = 0.f;
            __syncwarp();
            for (int k = lane; k < d; k += 32)
                mrow[__float_as_int(nav[k].x) >> 5] = navf[2 * k + 1];
        }
    }
}

// ---------------------------------------------------------------------------
extern "C" void kernel_launch(void* const* d_in, const int* in_sizes, int n_in,
                              void* d_out, int out_size)
{
    const float* X  = (const float*)d_in[0];
    const float* A  = (const float*)d_in[1];
    const float* K  = (const float*)d_in[2];
    const float* P  = (const float*)d_in[3];
    const float* FC = (const float*)d_in[4];
    const float* B1 = (const float*)d_in[5];
    const float* B2 = (const float*)d_in[6];
    float* out = (float*)d_out;

    const int smem_bytes =
        (N_*F_ + N_*KT_PITCH + N_*U_ + F_*U_ + 200 + 64 + 16 * 464) * 4; // 203152
    cudaFuncSetAttribute((const void*)gc_main,
                         cudaFuncAttributeMaxDynamicSharedMemorySize, smem_bytes);

    prep_kernel<<<N_, 128>>>(A, P);
    dim3 grid(H_, B_);
    gc_main<<<grid, 512, smem_bytes>>>(X, K, FC, B1, B2, out);
}